// round 7
// baseline (speedup 1.0000x reference)
#include <cuda_runtime.h>

// Problem constants
#define B_DIM 32
#define C_DIM 8
#define HW 65536              // 256*256
#define NPAIR 64              // B * (C/4)
#define BLOCKS_PER_PAIR 8
#define NBLOCKS (NPAIR * BLOCKS_PER_PAIR)   // 512  -> single wave @ 4 CTA/SM
#define NTHREADS 256
#define F4_PER_PLANE (HW / 4)               // 16384
#define F4_PER_BLOCK (F4_PER_PLANE / BLOCKS_PER_PAIR)  // 2048
#define NITER (F4_PER_BLOCK / NTHREADS)     // 8

// logit(0.7) = ln(7/3)
#define LOGIT_THRESH 0.8472978603872037f

// scratch: partial sums per block (msum, count, dnsum, bce) — fully
// overwritten every launch before being read; no zeroing needed.
__device__ float4 g_partials[NBLOCKS];
// completion counter: zero at module load; finisher resets it each launch.
__device__ unsigned int g_done_count;

__device__ __forceinline__ float4 warp_reduce4(float4 v) {
    #pragma unroll
    for (int o = 16; o > 0; o >>= 1) {
        v.x += __shfl_xor_sync(0xffffffffu, v.x, o);
        v.y += __shfl_xor_sync(0xffffffffu, v.y, o);
        v.z += __shfl_xor_sync(0xffffffffu, v.z, o);
        v.w += __shfl_xor_sync(0xffffffffu, v.w, o);
    }
    return v;
}

__device__ __forceinline__ void accum_pixel(
    float o0, float o1, float o2, float x,
    float t0, float t1, float t2, float t,
    float& msum, float& cnt, float& dnsum, float& bce)
{
    // L2 norm over the 3 image channels
    float dx = o0 - t0, dy = o1 - t1, dz = o2 - t2;
    float dn = sqrtf(fmaf(dx, dx, fmaf(dy, dy, dz * dz)));
    dnsum += dn;

    // BCE(sigmoid(x), t) with clipped logs:
    // s = log1p(exp(-|x|)); logp = -(max(-x,0)+s); log1mp = -(max(x,0)+s)
    float s = __logf(1.0f + __expf(-fabsf(x)));
    float logp  = -(fmaxf(-x, 0.0f) + s);
    float log1m = -(fmaxf( x, 0.0f) + s);
    logp  = fmaxf(logp,  -100.0f);
    log1m = fmaxf(log1m, -100.0f);
    bce += -(t * logp + (1.0f - t) * log1m);

    // mask: sigmoid(x) > 0.7  <=>  x > logit(0.7)
    float masked = (x > LOGIT_THRESH) ? dn : 0.0f;
    msum += masked;
    cnt  += (masked != 0.0f) ? 1.0f : 0.0f;
}

__global__ __launch_bounds__(NTHREADS, 4)
void lpml_fused_kernel(const float4* __restrict__ out4,
                       const float4* __restrict__ tar4,
                       float* __restrict__ final_out)
{
    // ---------------- finisher block ----------------
    if (blockIdx.x == NBLOCKS) {
        if (threadIdx.x == 0) {
            unsigned int v;
            do {
                asm volatile("ld.acquire.gpu.global.u32 %0, [%1];"
                             : "=r"(v) : "l"(&g_done_count));
            } while (v != NBLOCKS);
        }
        __syncthreads();   // all threads now see the partials (acquire + bar)

        const int t    = threadIdx.x;
        const int pair = t >> 2;        // 0..63
        const int sub  = t & 3;         // 0..3

        float ms = 0.f, c = 0.f, dns = 0.f, bc = 0.f;
        #pragma unroll
        for (int i = 0; i < 2; i++) {
            float4 p = g_partials[pair * BLOCKS_PER_PAIR + sub * 2 + i];
            ms += p.x; c += p.y; dns += p.z; bc += p.w;
        }
        #pragma unroll
        for (int o = 1; o <= 2; o <<= 1) {
            ms  += __shfl_xor_sync(0xffffffffu, ms,  o);
            c   += __shfl_xor_sync(0xffffffffu, c,   o);
            dns += __shfl_xor_sync(0xffffffffu, dns, o);
            bc  += __shfl_xor_sync(0xffffffffu, bc,  o);
        }

        __shared__ float contrib[NPAIR];
        if (sub == 0) {
            float fallback   = dns * (1.0f / (float)HW);
            float per_sample = (c > 0.0f) ? (ms / fmaxf(c, 1.0f)) : fallback;
            contrib[pair] = 0.7f * bc * (1.0f / ((float)B_DIM * (float)HW))
                          + 0.3f * per_sample * (1.0f / (float)B_DIM);
        }
        __syncthreads();

        if (t < 32) {
            float v = contrib[t] + contrib[t + 32];
            #pragma unroll
            for (int o = 16; o > 0; o >>= 1)
                v += __shfl_xor_sync(0xffffffffu, v, o);
            if (t == 0) {
                final_out[0] = v * 0.5f;
                g_done_count = 0;    // reset for next graph replay
            }
        }
        return;
    }

    // ---------------- worker blocks (equal work, single wave) ----------------
    const int pair = blockIdx.x >> 3;           // / BLOCKS_PER_PAIR
    const int blk  = blockIdx.x & 7;            // % BLOCKS_PER_PAIR
    const int b = pair >> 1;
    const int g = pair & 1;

    // base of channel 0 plane for (b, g), in float4 units
    const size_t base = (size_t)(b * C_DIM + g * 4) * F4_PER_PLANE;
    const int start = blk * F4_PER_BLOCK;

    float msum = 0.0f, cnt = 0.0f, dnsum = 0.0f, bce = 0.0f;

    #pragma unroll 2
    for (int it = 0; it < NITER; it++) {
        const int idx = start + it * NTHREADS + threadIdx.x;
        // streaming loads (no reuse -> evict-first)
        float4 o0 = __ldcs(&out4[base + 0 * F4_PER_PLANE + idx]);
        float4 o1 = __ldcs(&out4[base + 1 * F4_PER_PLANE + idx]);
        float4 o2 = __ldcs(&out4[base + 2 * F4_PER_PLANE + idx]);
        float4 o3 = __ldcs(&out4[base + 3 * F4_PER_PLANE + idx]);
        float4 t0 = __ldcs(&tar4[base + 0 * F4_PER_PLANE + idx]);
        float4 t1 = __ldcs(&tar4[base + 1 * F4_PER_PLANE + idx]);
        float4 t2 = __ldcs(&tar4[base + 2 * F4_PER_PLANE + idx]);
        float4 t3 = __ldcs(&tar4[base + 3 * F4_PER_PLANE + idx]);

        accum_pixel(o0.x, o1.x, o2.x, o3.x, t0.x, t1.x, t2.x, t3.x, msum, cnt, dnsum, bce);
        accum_pixel(o0.y, o1.y, o2.y, o3.y, t0.y, t1.y, t2.y, t3.y, msum, cnt, dnsum, bce);
        accum_pixel(o0.z, o1.z, o2.z, o3.z, t0.z, t1.z, t2.z, t3.z, msum, cnt, dnsum, bce);
        accum_pixel(o0.w, o1.w, o2.w, o3.w, t0.w, t1.w, t2.w, t3.w, msum, cnt, dnsum, bce);
    }

    // block reduction: warp shuffle, then cross-warp via shared
    float4 v = make_float4(msum, cnt, dnsum, bce);
    v = warp_reduce4(v);

    __shared__ float4 sm[NTHREADS / 32];
    const int wid = threadIdx.x >> 5;
    const int lid = threadIdx.x & 31;
    if (lid == 0) sm[wid] = v;
    __syncthreads();

    if (wid == 0) {
        float4 w = (lid < NTHREADS / 32) ? sm[lid] : make_float4(0.f, 0.f, 0.f, 0.f);
        w = warp_reduce4(w);
        if (lid == 0) {
            g_partials[blockIdx.x] = w;
            // release RMW: orders the partial store before the increment
            // becomes visible; fire-and-forget (no fence, no return).
            asm volatile("red.release.gpu.global.add.u32 [%0], %1;"
                         :: "l"(&g_done_count), "r"(1u) : "memory");
        }
    }
}

extern "C" void kernel_launch(void* const* d_in, const int* in_sizes, int n_in,
                              void* d_out, int out_size)
{
    const float4* out4 = (const float4*)d_in[0];
    const float4* tar4 = (const float4*)d_in[1];
    float* out = (float*)d_out;

    lpml_fused_kernel<<<NBLOCKS + 1, NTHREADS>>>(out4, tar4, out);
}

// round 11
// speedup vs baseline: 1.0849x; 1.0849x over previous
#include <cuda_runtime.h>

// Problem constants
#define B_DIM 32
#define C_DIM 8
#define HW 65536              // 256*256
#define NPAIR 64              // B * (C/4)
#define BLOCKS_PER_PAIR 16
#define NBLOCKS (NPAIR * BLOCKS_PER_PAIR)   // 1024 workers
#define NTHREADS 128
#define F4_PER_PLANE (HW / 4)               // 16384
#define F4_PER_BLOCK (F4_PER_PLANE / BLOCKS_PER_PAIR)  // 1024
#define STAGE_P 128                          // f4 positions per stage
#define NSTAGES (F4_PER_BLOCK / STAGE_P)     // 8

// logit(0.7) = ln(7/3)
#define LOGIT_THRESH 0.8472978603872037f

// scratch: per-block partials (msum, count, dnsum, bce); fully overwritten
// each launch before being read.
__device__ float4 g_partials[NBLOCKS];
// completion counter: zero at module load; finisher resets it each launch.
__device__ unsigned int g_done_count;

// ---------------- small helpers ----------------

__device__ __forceinline__ void cp16(float4* dst_smem, const float4* src_gmem) {
    unsigned sdst = (unsigned)__cvta_generic_to_shared(dst_smem);
    asm volatile("cp.async.cg.shared.global [%0], [%1], 16;\n"
                 :: "r"(sdst), "l"(src_gmem));
}
__device__ __forceinline__ void cp_commit() {
    asm volatile("cp.async.commit_group;\n");
}
template <int N>
__device__ __forceinline__ void cp_wait() {
    asm volatile("cp.async.wait_group %0;\n" :: "n"(N));
}

__device__ __forceinline__ float fsqrt_approx(float x) {
    float r;
    asm("sqrt.approx.f32 %0, %1;" : "=f"(r) : "f"(x));
    return r;
}

__device__ __forceinline__ void accum_pixel(
    float o0, float o1, float o2, float x,
    float t0, float t1, float t2, float t,
    float& msum, float& cnt, float& dnsum, float& bce)
{
    // L2 norm over the 3 image channels
    float dx = o0 - t0, dy = o1 - t1, dz = o2 - t2;
    float dn = fsqrt_approx(fmaf(dx, dx, fmaf(dy, dy, dz * dz)));
    dnsum += dn;

    // BCE(sigmoid(x), t): s = log1p(exp(-|x|));
    // logp = -(max(-x,0)+s); log1mp = -(max(x,0)+s); clip at -100
    float s = __logf(1.0f + __expf(-fabsf(x)));
    float logp  = fmaxf(-(fmaxf(-x, 0.0f) + s), -100.0f);
    float log1m = fmaxf(-(fmaxf( x, 0.0f) + s), -100.0f);
    bce += -(t * logp + (1.0f - t) * log1m);

    // mask: sigmoid(x) > 0.7  <=>  x > logit(0.7)
    float masked = (x > LOGIT_THRESH) ? dn : 0.0f;
    msum += masked;
    cnt  += (masked != 0.0f) ? 1.0f : 0.0f;
}

__global__ __launch_bounds__(NTHREADS)
void lpml_fused_kernel(const float4* __restrict__ out4,
                       const float4* __restrict__ tar4,
                       float* __restrict__ final_out)
{
    // ---------------- finisher block ----------------
    if (blockIdx.x == NBLOCKS) {
        if (threadIdx.x == 0) {
            unsigned int v;
            do {
                asm volatile("ld.acquire.gpu.global.u32 %0, [%1];"
                             : "=r"(v) : "l"(&g_done_count));
            } while (v != NBLOCKS);
        }
        __syncthreads();

        const int t    = threadIdx.x;      // 0..127
        const int pair = t >> 1;           // 0..63
        const int sub  = t & 1;            // 0..1

        float ms = 0.f, c = 0.f, dns = 0.f, bc = 0.f;
        #pragma unroll
        for (int i = 0; i < 8; i++) {
            float4 p = g_partials[pair * BLOCKS_PER_PAIR + sub * 8 + i];
            ms += p.x; c += p.y; dns += p.z; bc += p.w;
        }
        ms  += __shfl_xor_sync(0xffffffffu, ms,  1);
        c   += __shfl_xor_sync(0xffffffffu, c,   1);
        dns += __shfl_xor_sync(0xffffffffu, dns, 1);
        bc  += __shfl_xor_sync(0xffffffffu, bc,  1);

        __shared__ float contrib[NPAIR];
        if (sub == 0) {
            float fallback   = dns * (1.0f / (float)HW);
            float per_sample = (c > 0.0f) ? (ms / fmaxf(c, 1.0f)) : fallback;
            contrib[pair] = 0.7f * bc * (1.0f / ((float)B_DIM * (float)HW))
                          + 0.3f * per_sample * (1.0f / (float)B_DIM);
        }
        __syncthreads();

        if (t < 32) {
            float v = contrib[t] + contrib[t + 32];
            #pragma unroll
            for (int o = 16; o > 0; o >>= 1)
                v += __shfl_xor_sync(0xffffffffu, v, o);
            if (t == 0) {
                final_out[0] = v * 0.5f;
                g_done_count = 0;    // reset for next graph replay
            }
        }
        return;
    }

    // ---------------- worker blocks: cp.async pipelined ----------------
    // smem: [parity][stream 0..7][position]   (streams: o0..o3, t0..t3)
    __shared__ float4 buf[2][8][STAGE_P];

    const int pair = blockIdx.x >> 4;           // / BLOCKS_PER_PAIR
    const int blk  = blockIdx.x & 15;           // % BLOCKS_PER_PAIR
    const int b = pair >> 1;
    const int g = pair & 1;
    const int t = threadIdx.x;                  // 0..127 == position in stage

    // base of channel-0 plane for (b, g), in float4 units
    const size_t base = (size_t)(b * C_DIM + g * 4) * F4_PER_PLANE;
    const float4* po = out4 + base;
    const float4* pt = tar4 + base;
    const int start = blk * F4_PER_BLOCK;

    // thread t copies position t of all 8 streams, and consumes exactly
    // those -> per-thread pipeline, no __syncthreads needed.
    #define COPY_STAGE(stg, par)                                            \
        do {                                                                \
            const int gidx = start + (stg) * STAGE_P + t;                   \
            cp16(&buf[par][0][t], po + 0 * F4_PER_PLANE + gidx);            \
            cp16(&buf[par][1][t], po + 1 * F4_PER_PLANE + gidx);            \
            cp16(&buf[par][2][t], po + 2 * F4_PER_PLANE + gidx);            \
            cp16(&buf[par][3][t], po + 3 * F4_PER_PLANE + gidx);            \
            cp16(&buf[par][4][t], pt + 0 * F4_PER_PLANE + gidx);            \
            cp16(&buf[par][5][t], pt + 1 * F4_PER_PLANE + gidx);            \
            cp16(&buf[par][6][t], pt + 2 * F4_PER_PLANE + gidx);            \
            cp16(&buf[par][7][t], pt + 3 * F4_PER_PLANE + gidx);            \
            cp_commit();                                                    \
        } while (0)

    float msum = 0.0f, cnt = 0.0f, dnsum = 0.0f, bce = 0.0f;

    COPY_STAGE(0, 0);
    COPY_STAGE(1, 1);

    #pragma unroll
    for (int k = 0; k < NSTAGES; k++) {
        if (k < NSTAGES - 1) cp_wait<1>(); else cp_wait<0>();

        const int par = k & 1;
        float4 o0 = buf[par][0][t];
        float4 o1 = buf[par][1][t];
        float4 o2 = buf[par][2][t];
        float4 o3 = buf[par][3][t];
        float4 t0 = buf[par][4][t];
        float4 t1 = buf[par][5][t];
        float4 t2 = buf[par][6][t];
        float4 t3 = buf[par][7][t];

        accum_pixel(o0.x, o1.x, o2.x, o3.x, t0.x, t1.x, t2.x, t3.x, msum, cnt, dnsum, bce);
        accum_pixel(o0.y, o1.y, o2.y, o3.y, t0.y, t1.y, t2.y, t3.y, msum, cnt, dnsum, bce);
        accum_pixel(o0.z, o1.z, o2.z, o3.z, t0.z, t1.z, t2.z, t3.z, msum, cnt, dnsum, bce);
        accum_pixel(o0.w, o1.w, o2.w, o3.w, t0.w, t1.w, t2.w, t3.w, msum, cnt, dnsum, bce);

        if (k + 2 < NSTAGES) COPY_STAGE(k + 2, par);
    }
    #undef COPY_STAGE

    // block reduction: warp shuffle, then cross-warp via shared
    float m = msum, c = cnt, d = dnsum, e = bce;
    #pragma unroll
    for (int o = 16; o > 0; o >>= 1) {
        m += __shfl_xor_sync(0xffffffffu, m, o);
        c += __shfl_xor_sync(0xffffffffu, c, o);
        d += __shfl_xor_sync(0xffffffffu, d, o);
        e += __shfl_xor_sync(0xffffffffu, e, o);
    }

    __shared__ float4 sm[NTHREADS / 32];
    const int wid = t >> 5;
    const int lid = t & 31;
    if (lid == 0) sm[wid] = make_float4(m, c, d, e);
    __syncthreads();

    if (t < 32) {
        float4 w = (lid < NTHREADS / 32) ? sm[lid] : make_float4(0.f, 0.f, 0.f, 0.f);
        #pragma unroll
        for (int o = 2; o > 0; o >>= 1) {
            w.x += __shfl_xor_sync(0xffffffffu, w.x, o);
            w.y += __shfl_xor_sync(0xffffffffu, w.y, o);
            w.z += __shfl_xor_sync(0xffffffffu, w.z, o);
            w.w += __shfl_xor_sync(0xffffffffu, w.w, o);
        }
        if (lid == 0) {
            g_partials[blockIdx.x] = w;
            // release RMW: orders partial store before counter visibility
            asm volatile("red.release.gpu.global.add.u32 [%0], %1;"
                         :: "l"(&g_done_count), "r"(1u) : "memory");
        }
    }
}

extern "C" void kernel_launch(void* const* d_in, const int* in_sizes, int n_in,
                              void* d_out, int out_size)
{
    const float4* out4 = (const float4*)d_in[0];
    const float4* tar4 = (const float4*)d_in[1];
    float* out = (float*)d_out;

    lpml_fused_kernel<<<NBLOCKS + 1, NTHREADS>>>(out4, tar4, out);
}